// round 7
// baseline (speedup 1.0000x reference)
#include <cuda_runtime.h>
#include <math.h>

// B=2, D=H=W=128, C=4 image; label int32 C=1; coarse flow [2,4,4,4,3].
// Output: image [2,128,128,128,4] f32 then label [2,128,128,128] (as float).
// Intermediate flow (after resize+convD) stored PLANAR: [c][b][d][h][w]

#define NVOX      (2*128*128*128)
#define IMG_ELEMS (NVOX*4)
#define FLOW_N    (NVOX*3)

__device__ float d_F2[FLOW_N];  // after resize + convD, planar

// ---- weight generation (exact op structure jax/numpy use) ----
__device__ __forceinline__ float keys_f32(float x) {
    if (x < 1.0f) {
        float t = __fadd_rn(__fmul_rn(1.5f, x), -2.5f);
        t = __fmul_rn(t, x); t = __fmul_rn(t, x);
        return __fadd_rn(t, 1.0f);
    }
    if (x < 2.0f) {
        float t = __fadd_rn(__fmul_rn(-0.5f, x), 2.5f);
        t = __fadd_rn(__fmul_rn(t, x), -4.0f);
        t = __fmul_rn(t, x);
        return __fadd_rn(t, 2.0f);
    }
    return 0.0f;
}

__device__ __forceinline__ void gen_W_row(float* Wrow, int x) {
    float s = __fadd_rn(__fdiv_rn(__fadd_rn((float)x, 0.5f), 32.0f), -0.5f);
    float wv[4];
#pragma unroll
    for (int a = 0; a < 4; a++) wv[a] = keys_f32(fabsf(__fadd_rn(s, -(float)a)));
    float tot = __fadd_rn(__fadd_rn(__fadd_rn(wv[0], wv[1]), wv[2]), wv[3]);
#pragma unroll
    for (int a = 0; a < 4; a++) Wrow[a] = __fdiv_rn(wv[a], tot);
}

// ---------------- fused resizeD+resizeH+resizeW+convD (planar out) ----------------
// grid (4, 128, 2) = (d-tile of 32, h, b); 384 threads, planar mapping (c = t>>7, w = t&127)
__global__ __launch_bounds__(384) void flowD_kernel(const float* __restrict__ coarse) {
    __shared__ float  cf[192];
    __shared__ float  A2h[1536];     // [d'][e*3+c]
    __shared__ float  Ws[128][4];
    __shared__ float  Gs[16];
    __shared__ double gtmp[16];
    const int t = threadIdx.x;
    const int t0 = blockIdx.x * 32;
    const int h = blockIdx.y, b = blockIdx.z;

    if (t < 128) gen_W_row(Ws[t], t);
    if (t >= 128 && t < 144) { double o = (double)(t - 128 - 7); gtmp[t - 128] = exp(-o * o / 12.5); }
    if (t >= 192 && t < 384) cf[t - 192] = coarse[b * 192 + (t - 192)];
    __syncthreads();
    if (t < 16) {
        double gs = 0.0;
        for (int j = 0; j < 16; j++) gs += gtmp[j];
        Gs[t] = (float)(gtmp[t] / gs);
    }
    __syncthreads();

    // A2h[d'][ec] = sum_bb W[h][bb] * (sum_a W[d'][a] * cf[a][bb][ec])   (frozen fma order)
    const float wh0 = Ws[h][0], wh1 = Ws[h][1], wh2 = Ws[h][2], wh3 = Ws[h][3];
    for (int i = t; i < 1536; i += 384) {
        const int dp = i / 12, ec = i - dp * 12;
        float acc = 0.0f;
#pragma unroll
        for (int bb = 0; bb < 4; bb++) {
            float a1 = 0.0f;
#pragma unroll
            for (int a = 0; a < 4; a++)
                a1 = fmaf(Ws[dp][a], cf[a * 48 + bb * 12 + ec], a1);
            const float whb = (bb == 0) ? wh0 : (bb == 1) ? wh1 : (bb == 2) ? wh2 : wh3;
            acc = fmaf(whb, a1, acc);
        }
        A2h[i] = acc;
    }
    __syncthreads();

    const int c = t >> 7, w = t & 127;
    const float ww0 = Ws[w][0], ww1 = Ws[w][1], ww2 = Ws[w][2], ww3 = Ws[w][3];

    auto b1 = [&](int dp) -> float {   // zero outside [0,128) == tap-skip, bit-exact
        if (dp < 0 || dp >= 128) return 0.0f;
        const float* a2 = &A2h[dp * 12 + c];
        float acc = 0.0f;
        acc = fmaf(ww0, a2[0], acc);
        acc = fmaf(ww1, a2[3], acc);
        acc = fmaf(ww2, a2[6], acc);
        acc = fmaf(ww3, a2[9], acc);
        return acc;
    };

    float g[16];
#pragma unroll
    for (int j = 0; j < 16; j++) g[j] = Gs[j];

    float win[16];
#pragma unroll
    for (int j = 0; j < 16; j++) win[j] = b1(t0 - 7 + j);

    size_t obase = ((size_t)(c * 2 + b) << 21) + ((size_t)t0 << 14) + (h << 7) + w;
#pragma unroll
    for (int dl = 0; dl < 32; dl++) {
        float acc = 0.0f;
#pragma unroll
        for (int j = 0; j < 16; j++)
            acc = fmaf(g[j], win[(dl + j) & 15], acc);   // j ascending: bit-exact
        d_F2[obase] = acc;
        obase += 16384;
        if (dl < 31) win[dl & 15] = b1(t0 - 7 + dl + 16);
    }
}

// ---------------- fused convH + convW + warp (image trilinear + label nearest) --------
// grid (8, 128, 2) = (h-tile of 16, d, b); 384 threads
// dyn smem: IN [3][31][128] = 11904 floats; H [48][129] = 6192 floats at +11904.
// OUT (finished flow tile) reuses IN region as [48][129]  (pi = c*16+hl rows).
extern __shared__ float dyn_smem[];

__device__ __forceinline__ float4 lerp4(float4 p, float4 q, float t) {
    float4 r;
    r.x = fmaf(t, q.x - p.x, p.x);
    r.y = fmaf(t, q.y - p.y, p.y);
    r.z = fmaf(t, q.z - p.z, p.z);
    r.w = fmaf(t, q.w - p.w, p.w);
    return r;
}

__global__ __launch_bounds__(384) void flowHW_warp_kernel(
    const float* __restrict__ img, const int* __restrict__ lab, float* __restrict__ out)
{
    float* IN  = dyn_smem;
    float* H   = dyn_smem + 11904;
    float* OUT = dyn_smem;
    __shared__ float  Gs[16];
    __shared__ double gtmp[16];
    const int t = threadIdx.x;
    const int h0 = blockIdx.x * 16;
    const int d = blockIdx.y, b = blockIdx.z;

    if (t < 16) { double o = (double)(t - 7); gtmp[t] = exp(-o * o / 12.5); }
    __syncthreads();
    if (t < 16) {
        double gs = 0.0;
        for (int j = 0; j < 16; j++) gs += gtmp[j];
        Gs[t] = (float)(gtmp[t] / gs);
    }

    // phase 1: load 3 planes x 31 h-rows (zero-pad outside)
    for (int i = t; i < 3 * 31 * 128; i += 384) {
        const int c = i / 3968, rem = i - c * 3968, r = rem >> 7, w = rem & 127;
        const int hp = h0 - 7 + r;
        IN[i] = (hp >= 0 && hp < 128)
              ? d_F2[((size_t)(c * 2 + b) << 21) + ((size_t)d << 14) + (hp << 7) + w] : 0.0f;
    }
    __syncthreads();

    float g[16];
#pragma unroll
    for (int j = 0; j < 16; j++) g[j] = Gs[j];

    // phase 2: convH, sliding along h. thread = (c = t>>7, w = t&127)
    {
        const int c = t >> 7, w = t & 127;
        const float* col = IN + c * 3968 + w;
        float win[16];
#pragma unroll
        for (int j = 0; j < 16; j++) win[j] = col[j << 7];
#pragma unroll
        for (int hl = 0; hl < 16; hl++) {
            float acc = 0.0f;
#pragma unroll
            for (int j = 0; j < 16; j++)
                acc = fmaf(g[j], win[(hl + j) & 15], acc);
            H[(c * 16 + hl) * 129 + w] = acc;
            if (hl < 15) win[hl & 15] = col[(hl + 16) << 7];
        }
    }
    __syncthreads();

    // phase 3: convW, sliding along w. chunk-major: t = q*48 + pi (pi = c*16+hl)
    {
        const int q = t / 48, pi = t - q * 48;
        const int s0 = q * 16 - 7;
        const float* row = H + pi * 129;
        auto hv = [&](int s) -> float { return (s >= 0 && s < 128) ? row[s] : 0.0f; };
        float win[16];
#pragma unroll
        for (int j = 0; j < 16; j++) win[j] = hv(s0 + j);
        float* orow = OUT + pi * 129 + q * 16;
#pragma unroll
        for (int wl = 0; wl < 16; wl++) {
            float acc = 0.0f;
#pragma unroll
            for (int j = 0; j < 16; j++)
                acc = fmaf(g[j], win[(wl + j) & 15], acc);
            orow[wl] = acc;
            if (wl < 15) win[wl & 15] = hv(s0 + wl + 16);
        }
    }
    __syncthreads();

    // phase 4: warp — trilinear image + nearest label, flow straight from smem
    const float4* __restrict__ I = reinterpret_cast<const float4*>(img);
    const int bbase = b << 21;

    for (int i = t; i < 16 * 128; i += 384) {
        const int hl = i >> 7, w = i & 127;
        const int h = h0 + hl;

        const float f0 = OUT[( 0 + hl) * 129 + w];
        const float f1 = OUT[(16 + hl) * 129 + w];
        const float f2 = OUT[(32 + hl) * 129 + w];

        const float wd = __fadd_rn((float)d, __fmul_rn(f0, 35.0f));
        const float wh = __fadd_rn((float)h, __fmul_rn(f1, 35.0f));
        const float ww = __fadd_rn((float)w, __fmul_rn(f2, 35.0f));

        const float fld = floorf(wd), flh = floorf(wh), flw = floorf(ww);
        const float td = wd - fld, th = wh - flh, tw = ww - flw;

        const int id = (int)fld, ih = (int)flh, iw = (int)flw;
        const int d0 = min(max(id,     0), 127), d1 = min(max(id + 1, 0), 127);
        const int h0c = min(max(ih,    0), 127), h1c = min(max(ih + 1, 0), 127);
        const int w0 = min(max(iw,     0), 127), w1 = min(max(iw + 1, 0), 127);

        const int r00 = bbase + (d0 * 128 + h0c) * 128;
        const int r01 = bbase + (d0 * 128 + h1c) * 128;
        const int r10 = bbase + (d1 * 128 + h0c) * 128;
        const int r11 = bbase + (d1 * 128 + h1c) * 128;

        const float4 a000 = I[r00 + w0], a001 = I[r00 + w1];
        const float4 a010 = I[r01 + w0], a011 = I[r01 + w1];
        const float4 a100 = I[r10 + w0], a101 = I[r10 + w1];
        const float4 a110 = I[r11 + w0], a111 = I[r11 + w1];

        const float4 c00 = lerp4(a000, a001, tw);
        const float4 c01 = lerp4(a010, a011, tw);
        const float4 c10 = lerp4(a100, a101, tw);
        const float4 c11 = lerp4(a110, a111, tw);
        const float4 c0  = lerp4(c00, c01, th);
        const float4 c1  = lerp4(c10, c11, th);

        const int oidx = bbase + (d * 128 + h) * 128 + w;
        reinterpret_cast<float4*>(out)[oidx] = lerp4(c0, c1, td);

        const int nd = min(max((int)rintf(wd), 0), 127);
        const int nh = min(max((int)rintf(wh), 0), 127);
        const int nw = min(max((int)rintf(ww), 0), 127);
        out[IMG_ELEMS + oidx] = (float)__ldg(&lab[bbase + (nd * 128 + nh) * 128 + nw]);
    }
}

extern "C" void kernel_launch(void* const* d_in, const int* in_sizes, int n_in,
                              void* d_out, int out_size) {
    const float* img    = (const float*)d_in[0];
    const int*   lab    = (const int*)  d_in[1];
    const float* coarse = (const float*)d_in[2];
    float* out = (float*)d_out;

    const int hw_smem = (11904 + 6192) * (int)sizeof(float); // 72384 B
    static int attr_done = 0;
    if (!attr_done) {
        cudaFuncSetAttribute(flowHW_warp_kernel, cudaFuncAttributeMaxDynamicSharedMemorySize, hw_smem);
        attr_done = 1;
    }

    flowD_kernel<<<dim3(4, 128, 2), 384>>>(coarse);
    flowHW_warp_kernel<<<dim3(8, 128, 2), 384, hw_smem>>>(img, lab, out);
}

// round 9
// speedup vs baseline: 1.1634x; 1.1634x over previous
#include <cuda_runtime.h>
#include <math.h>

// B=2, D=H=W=128, C=4 image; label int32 C=1; coarse flow [2,4,4,4,3].
// Output: image [2,128,128,128,4] f32 then label [2,128,128,128] (as float).
// Intermediate flow PLANAR: [c][b][d][h][w]

#define NVOX      (2*128*128*128)
#define IMG_ELEMS (NVOX*4)
#define FLOW_N    (NVOX*3)

__device__ float d_F2[FLOW_N];  // after resize + convD, planar
__device__ float d_F3[FLOW_N];  // after convH + convW,   planar

// ---- weight generation (exact op structure jax/numpy use) ----
__device__ __forceinline__ float keys_f32(float x) {
    if (x < 1.0f) {
        float t = __fadd_rn(__fmul_rn(1.5f, x), -2.5f);
        t = __fmul_rn(t, x); t = __fmul_rn(t, x);
        return __fadd_rn(t, 1.0f);
    }
    if (x < 2.0f) {
        float t = __fadd_rn(__fmul_rn(-0.5f, x), 2.5f);
        t = __fadd_rn(__fmul_rn(t, x), -4.0f);
        t = __fmul_rn(t, x);
        return __fadd_rn(t, 2.0f);
    }
    return 0.0f;
}

__device__ __forceinline__ void gen_W_row(float* Wrow, int x) {
    float s = __fadd_rn(__fdiv_rn(__fadd_rn((float)x, 0.5f), 32.0f), -0.5f);
    float wv[4];
#pragma unroll
    for (int a = 0; a < 4; a++) wv[a] = keys_f32(fabsf(__fadd_rn(s, -(float)a)));
    float tot = __fadd_rn(__fadd_rn(__fadd_rn(wv[0], wv[1]), wv[2]), wv[3]);
#pragma unroll
    for (int a = 0; a < 4; a++) Wrow[a] = __fdiv_rn(wv[a], tot);
}

// ---------------- fused resizeD+resizeH+resizeW+convD (planar out) ----------------
__global__ __launch_bounds__(384) void flowD_kernel(const float* __restrict__ coarse) {
    __shared__ float  cf[192];
    __shared__ float  A2h[1536];
    __shared__ float  Ws[128][4];
    __shared__ float  Gs[16];
    __shared__ double gtmp[16];
    const int t = threadIdx.x;
    const int t0 = blockIdx.x * 32;
    const int h = blockIdx.y, b = blockIdx.z;

    if (t < 128) gen_W_row(Ws[t], t);
    if (t >= 128 && t < 144) { double o = (double)(t - 128 - 7); gtmp[t - 128] = exp(-o * o / 12.5); }
    if (t >= 192 && t < 384) cf[t - 192] = coarse[b * 192 + (t - 192)];
    __syncthreads();
    if (t < 16) {
        double gs = 0.0;
        for (int j = 0; j < 16; j++) gs += gtmp[j];
        Gs[t] = (float)(gtmp[t] / gs);
    }
    __syncthreads();

    const float wh0 = Ws[h][0], wh1 = Ws[h][1], wh2 = Ws[h][2], wh3 = Ws[h][3];
    for (int i = t; i < 1536; i += 384) {
        const int dp = i / 12, ec = i - dp * 12;
        float acc = 0.0f;
#pragma unroll
        for (int bb = 0; bb < 4; bb++) {
            float a1 = 0.0f;
#pragma unroll
            for (int a = 0; a < 4; a++)
                a1 = fmaf(Ws[dp][a], cf[a * 48 + bb * 12 + ec], a1);
            const float whb = (bb == 0) ? wh0 : (bb == 1) ? wh1 : (bb == 2) ? wh2 : wh3;
            acc = fmaf(whb, a1, acc);
        }
        A2h[i] = acc;
    }
    __syncthreads();

    const int c = t >> 7, w = t & 127;
    const float ww0 = Ws[w][0], ww1 = Ws[w][1], ww2 = Ws[w][2], ww3 = Ws[w][3];

    auto b1 = [&](int dp) -> float {
        if (dp < 0 || dp >= 128) return 0.0f;
        const float* a2 = &A2h[dp * 12 + c];
        float acc = 0.0f;
        acc = fmaf(ww0, a2[0], acc);
        acc = fmaf(ww1, a2[3], acc);
        acc = fmaf(ww2, a2[6], acc);
        acc = fmaf(ww3, a2[9], acc);
        return acc;
    };

    float g[16];
#pragma unroll
    for (int j = 0; j < 16; j++) g[j] = Gs[j];

    float win[16];
#pragma unroll
    for (int j = 0; j < 16; j++) win[j] = b1(t0 - 7 + j);

    size_t obase = ((size_t)(c * 2 + b) << 21) + ((size_t)t0 << 14) + (h << 7) + w;
#pragma unroll
    for (int dl = 0; dl < 32; dl++) {
        float acc = 0.0f;
#pragma unroll
        for (int j = 0; j < 16; j++)
            acc = fmaf(g[j], win[(dl + j) & 15], acc);
        d_F2[obase] = acc;
        obase += 16384;
        if (dl < 31) win[dl & 15] = b1(t0 - 7 + dl + 16);
    }
}

// ---------------- fused convH + convW (planar, conflict-free sliding windows) --------
extern __shared__ float dyn_smem[];
__global__ __launch_bounds__(384) void flowHW_kernel() {
    float* IN = dyn_smem;
    float* H  = dyn_smem + 11904;
    float* OUT = dyn_smem;
    __shared__ float  Gs[16];
    __shared__ double gtmp[16];
    const int t = threadIdx.x;
    const int h0 = blockIdx.x * 16;
    const int d = blockIdx.y, b = blockIdx.z;

    if (t < 16) { double o = (double)(t - 7); gtmp[t] = exp(-o * o / 12.5); }
    __syncthreads();
    if (t < 16) {
        double gs = 0.0;
        for (int j = 0; j < 16; j++) gs += gtmp[j];
        Gs[t] = (float)(gtmp[t] / gs);
    }

    for (int i = t; i < 3 * 31 * 128; i += 384) {
        const int c = i / 3968, rem = i - c * 3968, r = rem >> 7, w = rem & 127;
        const int hp = h0 - 7 + r;
        IN[i] = (hp >= 0 && hp < 128)
              ? d_F2[((size_t)(c * 2 + b) << 21) + ((size_t)d << 14) + (hp << 7) + w] : 0.0f;
    }
    __syncthreads();

    float g[16];
#pragma unroll
    for (int j = 0; j < 16; j++) g[j] = Gs[j];

    {
        const int c = t >> 7, w = t & 127;
        const float* col = IN + c * 3968 + w;
        float win[16];
#pragma unroll
        for (int j = 0; j < 16; j++) win[j] = col[j << 7];
#pragma unroll
        for (int hl = 0; hl < 16; hl++) {
            float acc = 0.0f;
#pragma unroll
            for (int j = 0; j < 16; j++)
                acc = fmaf(g[j], win[(hl + j) & 15], acc);
            H[(c * 16 + hl) * 129 + w] = acc;
            if (hl < 15) win[hl & 15] = col[(hl + 16) << 7];
        }
    }
    __syncthreads();

    {
        const int q = t / 48, pi = t - q * 48;
        const int s0 = q * 16 - 7;
        const float* row = H + pi * 129;
        auto hv = [&](int s) -> float { return (s >= 0 && s < 128) ? row[s] : 0.0f; };
        float win[16];
#pragma unroll
        for (int j = 0; j < 16; j++) win[j] = hv(s0 + j);
        float* orow = OUT + pi * 129 + q * 16;
#pragma unroll
        for (int wl = 0; wl < 16; wl++) {
            float acc = 0.0f;
#pragma unroll
            for (int j = 0; j < 16; j++)
                acc = fmaf(g[j], win[(wl + j) & 15], acc);
            orow[wl] = acc;
            if (wl < 15) win[wl & 15] = hv(s0 + wl + 16);
        }
    }
    __syncthreads();

    {
        const int c = t >> 7, w = t & 127;
        const size_t gbase = ((size_t)(c * 2 + b) << 21) + ((size_t)d << 14) + w;
#pragma unroll
        for (int hl = 0; hl < 16; hl++)
            d_F3[gbase + ((h0 + hl) << 7)] = OUT[(c * 16 + hl) * 129 + w];
    }
}

// ---------------- warp: d-pair per thread, trilinear + nearest ----------------
__device__ __forceinline__ float4 lerp4(float4 p, float4 q, float t) {
    float4 r;
    r.x = fmaf(t, q.x - p.x, p.x);
    r.y = fmaf(t, q.y - p.y, p.y);
    r.z = fmaf(t, q.z - p.z, p.z);
    r.w = fmaf(t, q.w - p.w, p.w);
    return r;
}

// grid (32, 64, 2) = (h-quad, d-pair, b); 512 threads = 4 h x 128 w; each thread does d and d+1
// fl layout: [dd][c][hl][w] with strides 1536 / 512 / 128 / 1
__global__ __launch_bounds__(512, 2) void warp_kernel(
    const float* __restrict__ img, const int* __restrict__ lab, float* __restrict__ out)
{
    __shared__ float fl[2 * 3 * 4 * 128];
    const int t = threadIdx.x;
    const int dA = blockIdx.y * 2, b = blockIdx.z;
    const int h0t = blockIdx.x * 4;

    for (int i = t; i < 3072; i += 512) {
        const int dd = i / 1536, rem = i - dd * 1536;
        const int c = rem >> 9, rem2 = rem & 511;
        const int hl2 = rem2 >> 7, w2 = rem2 & 127;
        fl[i] = d_F3[((size_t)(c * 2 + b) << 21) + ((size_t)(dA + dd) << 14) + ((h0t + hl2) << 7) + w2];
    }
    __syncthreads();

    const int hl = t >> 7, w = t & 127;
    const int h = h0t + hl;
    const float4* __restrict__ I = reinterpret_cast<const float4*>(img);
    const int bbase = b << 21;

    // ---------- voxel A (depth dA) ----------
    const float wdA = __fadd_rn((float)dA, __fmul_rn(fl[          hl * 128 + w], 35.0f));
    const float whA = __fadd_rn((float)h,  __fmul_rn(fl[ 512 +    hl * 128 + w], 35.0f));
    const float wwA = __fadd_rn((float)w,  __fmul_rn(fl[1024 +    hl * 128 + w], 35.0f));

    const float fldA = floorf(wdA), flhA = floorf(whA), flwA = floorf(wwA);
    const float tdA = wdA - fldA, thA = whA - flhA, twA = wwA - flwA;
    const int idA = (int)fldA, ihA = (int)flhA, iwA = (int)flwA;

    const int d0A = min(max(idA,     0), 127), d1A = min(max(idA + 1, 0), 127);
    const int h0A = min(max(ihA,     0), 127), h1A = min(max(ihA + 1, 0), 127);
    const int w0A = min(max(iwA,     0), 127), w1A = min(max(iwA + 1, 0), 127);

    const int rA00 = bbase + (d0A * 128 + h0A) * 128;
    const int rA01 = bbase + (d0A * 128 + h1A) * 128;
    const int rA10 = bbase + (d1A * 128 + h0A) * 128;
    const int rA11 = bbase + (d1A * 128 + h1A) * 128;

    const float4 a000 = I[rA00 + w0A], a001 = I[rA00 + w1A];
    const float4 a010 = I[rA01 + w0A], a011 = I[rA01 + w1A];
    const float4 a100 = I[rA10 + w0A], a101 = I[rA10 + w1A];
    const float4 a110 = I[rA11 + w0A], a111 = I[rA11 + w1A];

    {
        const float4 c00 = lerp4(a000, a001, twA);
        const float4 c01 = lerp4(a010, a011, twA);
        const float4 c10 = lerp4(a100, a101, twA);
        const float4 c11 = lerp4(a110, a111, twA);
        const float4 c0  = lerp4(c00, c01, thA);
        const float4 c1  = lerp4(c10, c11, thA);
        const int oidx = bbase + (dA * 128 + h) * 128 + w;
        __stcs(&reinterpret_cast<float4*>(out)[oidx], lerp4(c0, c1, tdA));

        const int nd = min(max((int)rintf(wdA), 0), 127);
        const int nh = min(max((int)rintf(whA), 0), 127);
        const int nw = min(max((int)rintf(wwA), 0), 127);
        __stcs(&out[IMG_ELEMS + oidx], (float)__ldg(&lab[bbase + (nd * 128 + nh) * 128 + nw]));
    }

    // ---------- voxel B (depth dA+1), reuse A's upper plane when indices coincide ----------
    const int dB = dA + 1;
    const float wdB = __fadd_rn((float)dB, __fmul_rn(fl[1536 +        hl * 128 + w], 35.0f));
    const float whB = __fadd_rn((float)h,  __fmul_rn(fl[1536 + 512 +  hl * 128 + w], 35.0f));
    const float wwB = __fadd_rn((float)w,  __fmul_rn(fl[1536 + 1024 + hl * 128 + w], 35.0f));

    const float fldB = floorf(wdB), flhB = floorf(whB), flwB = floorf(wwB);
    const float tdB = wdB - fldB, thB = whB - flhB, twB = wwB - flwB;
    const int idB = (int)fldB, ihB = (int)flhB, iwB = (int)flwB;

    const int d0B = min(max(idB,     0), 127), d1B = min(max(idB + 1, 0), 127);
    const int h0B = min(max(ihB,     0), 127), h1B = min(max(ihB + 1, 0), 127);
    const int w0B = min(max(iwB,     0), 127), w1B = min(max(iwB + 1, 0), 127);

    const bool share = (d0B == d1A) && (h0B == h0A) && (h1B == h1A) && (w0B == w0A) && (w1B == w1A);

    float4 b000, b001, b010, b011;
    if (share) {
        b000 = a100; b001 = a101; b010 = a110; b011 = a111;
    } else {
        const int rB00 = bbase + (d0B * 128 + h0B) * 128;
        const int rB01 = bbase + (d0B * 128 + h1B) * 128;
        b000 = I[rB00 + w0B]; b001 = I[rB00 + w1B];
        b010 = I[rB01 + w0B]; b011 = I[rB01 + w1B];
    }
    const int rB10 = bbase + (d1B * 128 + h0B) * 128;
    const int rB11 = bbase + (d1B * 128 + h1B) * 128;
    const float4 b100 = I[rB10 + w0B], b101 = I[rB10 + w1B];
    const float4 b110 = I[rB11 + w0B], b111 = I[rB11 + w1B];

    {
        const float4 c00 = lerp4(b000, b001, twB);
        const float4 c01 = lerp4(b010, b011, twB);
        const float4 c10 = lerp4(b100, b101, twB);
        const float4 c11 = lerp4(b110, b111, twB);
        const float4 c0  = lerp4(c00, c01, thB);
        const float4 c1  = lerp4(c10, c11, thB);
        const int oidx = bbase + (dB * 128 + h) * 128 + w;
        __stcs(&reinterpret_cast<float4*>(out)[oidx], lerp4(c0, c1, tdB));

        const int nd = min(max((int)rintf(wdB), 0), 127);
        const int nh = min(max((int)rintf(whB), 0), 127);
        const int nw = min(max((int)rintf(wwB), 0), 127);
        __stcs(&out[IMG_ELEMS + oidx], (float)__ldg(&lab[bbase + (nd * 128 + nh) * 128 + nw]));
    }
}

extern "C" void kernel_launch(void* const* d_in, const int* in_sizes, int n_in,
                              void* d_out, int out_size) {
    const float* img    = (const float*)d_in[0];
    const int*   lab    = (const int*)  d_in[1];
    const float* coarse = (const float*)d_in[2];
    float* out = (float*)d_out;

    const int hw_smem = (11904 + 6192) * (int)sizeof(float); // 72384 B
    static int attr_done = 0;
    if (!attr_done) {
        cudaFuncSetAttribute(flowHW_kernel, cudaFuncAttributeMaxDynamicSharedMemorySize, hw_smem);
        attr_done = 1;
    }

    flowD_kernel<<<dim3(4, 128, 2), 384>>>(coarse);
    flowHW_kernel<<<dim3(8, 128, 2), 384, hw_smem>>>();
    warp_kernel<<<dim3(32, 64, 2), 512>>>(img, lab, out);
}

// round 10
// speedup vs baseline: 1.2176x; 1.0466x over previous
#include <cuda_runtime.h>
#include <math.h>

// B=2, D=H=W=128, C=4 image; label int32 C=1; coarse flow [2,4,4,4,3].
// Output: image [2,128,128,128,4] f32 then label [2,128,128,128] (as float).
// Intermediate flow PLANAR: [c][b][d][h][w]

#define NVOX      (2*128*128*128)
#define IMG_ELEMS (NVOX*4)
#define FLOW_N    (NVOX*3)

__device__ float d_F2[FLOW_N];  // after resize + convD, planar
__device__ float d_F3[FLOW_N];  // after convH + convW,   planar

// ---- weight generation (exact op structure jax/numpy use) ----
__device__ __forceinline__ float keys_f32(float x) {
    if (x < 1.0f) {
        float t = __fadd_rn(__fmul_rn(1.5f, x), -2.5f);
        t = __fmul_rn(t, x); t = __fmul_rn(t, x);
        return __fadd_rn(t, 1.0f);
    }
    if (x < 2.0f) {
        float t = __fadd_rn(__fmul_rn(-0.5f, x), 2.5f);
        t = __fadd_rn(__fmul_rn(t, x), -4.0f);
        t = __fmul_rn(t, x);
        return __fadd_rn(t, 2.0f);
    }
    return 0.0f;
}

__device__ __forceinline__ void gen_W_row(float* Wrow, int x) {
    float s = __fadd_rn(__fdiv_rn(__fadd_rn((float)x, 0.5f), 32.0f), -0.5f);
    float wv[4];
#pragma unroll
    for (int a = 0; a < 4; a++) wv[a] = keys_f32(fabsf(__fadd_rn(s, -(float)a)));
    float tot = __fadd_rn(__fadd_rn(__fadd_rn(wv[0], wv[1]), wv[2]), wv[3]);
#pragma unroll
    for (int a = 0; a < 4; a++) Wrow[a] = __fdiv_rn(wv[a], tot);
}

// ---------------- fused resizeD+resizeH+resizeW+convD (planar out) ----------------
// A2h computed ONLY for the 48 dp rows this block's window needs (local row = dp-(t0-7)).
__global__ __launch_bounds__(384) void flowD_kernel(const float* __restrict__ coarse) {
    __shared__ float  cf[192];
    __shared__ float  A2h[48 * 12];
    __shared__ float  Ws[128][4];
    __shared__ float  Gs[16];
    __shared__ double gtmp[16];
    const int t = threadIdx.x;
    const int t0 = blockIdx.x * 32;
    const int h = blockIdx.y, b = blockIdx.z;
    const int dplo = t0 - 7;           // first dp in window

    if (t < 128) gen_W_row(Ws[t], t);
    if (t >= 128 && t < 144) { double o = (double)(t - 128 - 7); gtmp[t - 128] = exp(-o * o / 12.5); }
    if (t >= 192 && t < 384) cf[t - 192] = coarse[b * 192 + (t - 192)];
    __syncthreads();
    if (t < 16) {
        double gs = 0.0;
        for (int j = 0; j < 16; j++) gs += gtmp[j];
        Gs[t] = (float)(gtmp[t] / gs);
    }
    __syncthreads();

    const float wh0 = Ws[h][0], wh1 = Ws[h][1], wh2 = Ws[h][2], wh3 = Ws[h][3];
    for (int i = t; i < 48 * 12; i += 384) {
        const int ld = i / 12, ec = i - ld * 12;
        const int dp = dplo + ld;
        float acc = 0.0f;
        if (dp >= 0 && dp < 128) {
#pragma unroll
            for (int bb = 0; bb < 4; bb++) {
                float a1 = 0.0f;
#pragma unroll
                for (int a = 0; a < 4; a++)
                    a1 = fmaf(Ws[dp][a], cf[a * 48 + bb * 12 + ec], a1);
                const float whb = (bb == 0) ? wh0 : (bb == 1) ? wh1 : (bb == 2) ? wh2 : wh3;
                acc = fmaf(whb, a1, acc);
            }
        }
        A2h[i] = acc;
    }
    __syncthreads();

    const int c = t >> 7, w = t & 127;
    const float ww0 = Ws[w][0], ww1 = Ws[w][1], ww2 = Ws[w][2], ww3 = Ws[w][3];

    auto b1 = [&](int ld) -> float {   // ld = local row; zero rows already zeroed above
        const int dp = dplo + ld;
        if (dp < 0 || dp >= 128) return 0.0f;
        const float* a2 = &A2h[ld * 12 + c];
        float acc = 0.0f;
        acc = fmaf(ww0, a2[0], acc);
        acc = fmaf(ww1, a2[3], acc);
        acc = fmaf(ww2, a2[6], acc);
        acc = fmaf(ww3, a2[9], acc);
        return acc;
    };

    float g[16];
#pragma unroll
    for (int j = 0; j < 16; j++) g[j] = Gs[j];

    float win[16];
#pragma unroll
    for (int j = 0; j < 16; j++) win[j] = b1(j);

    size_t obase = ((size_t)(c * 2 + b) << 21) + ((size_t)t0 << 14) + (h << 7) + w;
#pragma unroll
    for (int dl = 0; dl < 32; dl++) {
        float acc = 0.0f;
#pragma unroll
        for (int j = 0; j < 16; j++)
            acc = fmaf(g[j], win[(dl + j) & 15], acc);   // j ascending: bit-exact
        d_F2[obase] = acc;
        obase += 16384;
        if (dl < 31) win[dl & 15] = b1(dl + 16);
    }
}

// ---------------- fused convH + convW (planar, conflict-free sliding windows) --------
extern __shared__ float dyn_smem[];
__global__ __launch_bounds__(384) void flowHW_kernel() {
    float* IN = dyn_smem;
    float* H  = dyn_smem + 11904;
    float* OUT = dyn_smem;
    __shared__ float  Gs[16];
    __shared__ double gtmp[16];
    const int t = threadIdx.x;
    const int h0 = blockIdx.x * 16;
    const int d = blockIdx.y, b = blockIdx.z;

    if (t < 16) { double o = (double)(t - 7); gtmp[t] = exp(-o * o / 12.5); }
    __syncthreads();
    if (t < 16) {
        double gs = 0.0;
        for (int j = 0; j < 16; j++) gs += gtmp[j];
        Gs[t] = (float)(gtmp[t] / gs);
    }

    for (int i = t; i < 3 * 31 * 128; i += 384) {
        const int c = i / 3968, rem = i - c * 3968, r = rem >> 7, w = rem & 127;
        const int hp = h0 - 7 + r;
        IN[i] = (hp >= 0 && hp < 128)
              ? d_F2[((size_t)(c * 2 + b) << 21) + ((size_t)d << 14) + (hp << 7) + w] : 0.0f;
    }
    __syncthreads();

    float g[16];
#pragma unroll
    for (int j = 0; j < 16; j++) g[j] = Gs[j];

    {
        const int c = t >> 7, w = t & 127;
        const float* col = IN + c * 3968 + w;
        float win[16];
#pragma unroll
        for (int j = 0; j < 16; j++) win[j] = col[j << 7];
#pragma unroll
        for (int hl = 0; hl < 16; hl++) {
            float acc = 0.0f;
#pragma unroll
            for (int j = 0; j < 16; j++)
                acc = fmaf(g[j], win[(hl + j) & 15], acc);
            H[(c * 16 + hl) * 129 + w] = acc;
            if (hl < 15) win[hl & 15] = col[(hl + 16) << 7];
        }
    }
    __syncthreads();

    {
        const int q = t / 48, pi = t - q * 48;
        const int s0 = q * 16 - 7;
        const float* row = H + pi * 129;
        auto hv = [&](int s) -> float { return (s >= 0 && s < 128) ? row[s] : 0.0f; };
        float win[16];
#pragma unroll
        for (int j = 0; j < 16; j++) win[j] = hv(s0 + j);
        float* orow = OUT + pi * 129 + q * 16;
#pragma unroll
        for (int wl = 0; wl < 16; wl++) {
            float acc = 0.0f;
#pragma unroll
            for (int j = 0; j < 16; j++)
                acc = fmaf(g[j], win[(wl + j) & 15], acc);
            orow[wl] = acc;
            if (wl < 15) win[wl & 15] = hv(s0 + wl + 16);
        }
    }
    __syncthreads();

    {
        const int c = t >> 7, w = t & 127;
        const size_t gbase = ((size_t)(c * 2 + b) << 21) + ((size_t)d << 14) + w;
#pragma unroll
        for (int hl = 0; hl < 16; hl++)
            d_F3[gbase + ((h0 + hl) << 7)] = OUT[(c * 16 + hl) * 129 + w];
    }
}

// ---------------- warp: shuffle-shared gather, trilinear + nearest ----------------
__device__ __forceinline__ float4 lerp4(float4 p, float4 q, float t) {
    float4 r;
    r.x = fmaf(t, q.x - p.x, p.x);
    r.y = fmaf(t, q.y - p.y, p.y);
    r.z = fmaf(t, q.z - p.z, p.z);
    r.w = fmaf(t, q.w - p.w, p.w);
    return r;
}

// Load pair (v0 = I[idx0], v1 = I[idx1]); v1 comes from lane+1's v0 when the flat
// indices line up exactly (bit-identical to loading), else a real load.
__device__ __forceinline__ void gather_pair(
    const float4* __restrict__ I, int idx0, int idx1, float4& v0, float4& v1)
{
    v0 = I[idx0];
    const int nidx = __shfl_down_sync(0xffffffffu, idx0, 1);
    float4 cand;
    cand.x = __shfl_down_sync(0xffffffffu, v0.x, 1);
    cand.y = __shfl_down_sync(0xffffffffu, v0.y, 1);
    cand.z = __shfl_down_sync(0xffffffffu, v0.z, 1);
    cand.w = __shfl_down_sync(0xffffffffu, v0.w, 1);
    if (nidx == idx1 && (threadIdx.x & 31) != 31) {
        v1 = cand;
    } else {
        v1 = I[idx1];
    }
}

// grid (32, 128, 2) = (h-quad, d, b); 512 threads = 4 h-pencils x 128 w (lanes = consecutive w)
__global__ __launch_bounds__(512) void warp_kernel(
    const float* __restrict__ img, const int* __restrict__ lab, float* __restrict__ out)
{
    __shared__ float fl[3 * 4 * 128];   // [c][hl][w]
    const int t = threadIdx.x;
    const int d = blockIdx.y, b = blockIdx.z;

    for (int i = t; i < 1536; i += 512) {
        const int c = i >> 9, rem = i & 511, hl2 = rem >> 7, w2 = rem & 127;
        fl[i] = d_F3[((size_t)(c * 2 + b) << 21) + ((size_t)d << 14) + ((blockIdx.x * 4 + hl2) << 7) + w2];
    }
    __syncthreads();

    const int hl = t >> 7, w = t & 127;
    const int h = blockIdx.x * 4 + hl;

    const float f0 = fl[          hl * 128 + w];
    const float f1 = fl[ 512 +    hl * 128 + w];
    const float f2 = fl[1024 +    hl * 128 + w];

    const float wd = __fadd_rn((float)d, __fmul_rn(f0, 35.0f));
    const float wh = __fadd_rn((float)h, __fmul_rn(f1, 35.0f));
    const float ww = __fadd_rn((float)w, __fmul_rn(f2, 35.0f));

    const float fld = floorf(wd), flh = floorf(wh), flw = floorf(ww);
    const float td = wd - fld, th = wh - flh, tw = ww - flw;

    const int id = (int)fld, ih = (int)flh, iw = (int)flw;
    const int d0 = min(max(id,     0), 127), d1 = min(max(id + 1, 0), 127);
    const int h0 = min(max(ih,     0), 127), h1 = min(max(ih + 1, 0), 127);
    const int w0 = min(max(iw,     0), 127), w1 = min(max(iw + 1, 0), 127);

    const float4* __restrict__ I = reinterpret_cast<const float4*>(img);
    const int bbase = b << 21;

    const int r00 = bbase + (d0 * 128 + h0) * 128;
    const int r01 = bbase + (d0 * 128 + h1) * 128;
    const int r10 = bbase + (d1 * 128 + h0) * 128;
    const int r11 = bbase + (d1 * 128 + h1) * 128;

    float4 a000, a001, a010, a011, a100, a101, a110, a111;
    gather_pair(I, r00 + w0, r00 + w1, a000, a001);
    gather_pair(I, r01 + w0, r01 + w1, a010, a011);
    gather_pair(I, r10 + w0, r10 + w1, a100, a101);
    gather_pair(I, r11 + w0, r11 + w1, a110, a111);

    const float4 c00 = lerp4(a000, a001, tw);
    const float4 c01 = lerp4(a010, a011, tw);
    const float4 c10 = lerp4(a100, a101, tw);
    const float4 c11 = lerp4(a110, a111, tw);
    const float4 c0  = lerp4(c00, c01, th);
    const float4 c1  = lerp4(c10, c11, th);

    const int oidx = bbase + (d * 128 + h) * 128 + w;
    reinterpret_cast<float4*>(out)[oidx] = lerp4(c0, c1, td);

    const int nd = min(max((int)rintf(wd), 0), 127);
    const int nh = min(max((int)rintf(wh), 0), 127);
    const int nw = min(max((int)rintf(ww), 0), 127);
    out[IMG_ELEMS + oidx] = (float)__ldg(&lab[bbase + (nd * 128 + nh) * 128 + nw]);
}

extern "C" void kernel_launch(void* const* d_in, const int* in_sizes, int n_in,
                              void* d_out, int out_size) {
    const float* img    = (const float*)d_in[0];
    const int*   lab    = (const int*)  d_in[1];
    const float* coarse = (const float*)d_in[2];
    float* out = (float*)d_out;

    const int hw_smem = (11904 + 6192) * (int)sizeof(float); // 72384 B
    static int attr_done = 0;
    if (!attr_done) {
        cudaFuncSetAttribute(flowHW_kernel, cudaFuncAttributeMaxDynamicSharedMemorySize, hw_smem);
        attr_done = 1;
    }

    flowD_kernel<<<dim3(4, 128, 2), 384>>>(coarse);
    flowHW_kernel<<<dim3(8, 128, 2), 384, hw_smem>>>();
    warp_kernel<<<dim3(32, 128, 2), 512>>>(img, lab, out);
}

// round 11
// speedup vs baseline: 1.5295x; 1.2561x over previous
#include <cuda_runtime.h>
#include <math.h>

// B=2, D=H=W=128, C=4 image; label int32 C=1; coarse flow [2,4,4,4,3].
// Output: image [2,128,128,128,4] f32 then label [2,128,128,128] (as float).
// Intermediate flow PLANAR: [c][b][d][h][w]

#define NVOX      (2*128*128*128)
#define IMG_ELEMS (NVOX*4)
#define FLOW_N    (NVOX*3)

__device__ float d_F2[FLOW_N];  // after resize + convD, planar
__device__ float d_F3[FLOW_N];  // after convH + convW,   planar

// ---- weight generation (exact op structure jax/numpy use) ----
__device__ __forceinline__ float keys_f32(float x) {
    if (x < 1.0f) {
        float t = __fadd_rn(__fmul_rn(1.5f, x), -2.5f);
        t = __fmul_rn(t, x); t = __fmul_rn(t, x);
        return __fadd_rn(t, 1.0f);
    }
    if (x < 2.0f) {
        float t = __fadd_rn(__fmul_rn(-0.5f, x), 2.5f);
        t = __fadd_rn(__fmul_rn(t, x), -4.0f);
        t = __fmul_rn(t, x);
        return __fadd_rn(t, 2.0f);
    }
    return 0.0f;
}

__device__ __forceinline__ void gen_W_row(float* Wrow, int x) {
    float s = __fadd_rn(__fdiv_rn(__fadd_rn((float)x, 0.5f), 32.0f), -0.5f);
    float wv[4];
#pragma unroll
    for (int a = 0; a < 4; a++) wv[a] = keys_f32(fabsf(__fadd_rn(s, -(float)a)));
    float tot = __fadd_rn(__fadd_rn(__fadd_rn(wv[0], wv[1]), wv[2]), wv[3]);
#pragma unroll
    for (int a = 0; a < 4; a++) Wrow[a] = __fdiv_rn(wv[a], tot);
}

// ---------------- fused resizeD+resizeH+resizeW+convD (planar out) ----------------
// A2h computed ONLY for the 48 dp rows this block's window needs.
__global__ __launch_bounds__(384) void flowD_kernel(const float* __restrict__ coarse) {
    __shared__ float  cf[192];
    __shared__ float  A2h[48 * 12];
    __shared__ float  Ws[128][4];
    __shared__ float  Gs[16];
    __shared__ double gtmp[16];
    const int t = threadIdx.x;
    const int t0 = blockIdx.x * 32;
    const int h = blockIdx.y, b = blockIdx.z;
    const int dplo = t0 - 7;

    if (t < 128) gen_W_row(Ws[t], t);
    if (t >= 128 && t < 144) { double o = (double)(t - 128 - 7); gtmp[t - 128] = exp(-o * o / 12.5); }
    if (t >= 192 && t < 384) cf[t - 192] = coarse[b * 192 + (t - 192)];
    __syncthreads();
    if (t < 16) {
        double gs = 0.0;
        for (int j = 0; j < 16; j++) gs += gtmp[j];
        Gs[t] = (float)(gtmp[t] / gs);
    }
    __syncthreads();

    const float wh0 = Ws[h][0], wh1 = Ws[h][1], wh2 = Ws[h][2], wh3 = Ws[h][3];
    for (int i = t; i < 48 * 12; i += 384) {
        const int ld = i / 12, ec = i - ld * 12;
        const int dp = dplo + ld;
        float acc = 0.0f;
        if (dp >= 0 && dp < 128) {
#pragma unroll
            for (int bb = 0; bb < 4; bb++) {
                float a1 = 0.0f;
#pragma unroll
                for (int a = 0; a < 4; a++)
                    a1 = fmaf(Ws[dp][a], cf[a * 48 + bb * 12 + ec], a1);
                const float whb = (bb == 0) ? wh0 : (bb == 1) ? wh1 : (bb == 2) ? wh2 : wh3;
                acc = fmaf(whb, a1, acc);
            }
        }
        A2h[i] = acc;
    }
    __syncthreads();

    const int c = t >> 7, w = t & 127;
    const float ww0 = Ws[w][0], ww1 = Ws[w][1], ww2 = Ws[w][2], ww3 = Ws[w][3];

    auto b1 = [&](int ld) -> float {
        const int dp = dplo + ld;
        if (dp < 0 || dp >= 128) return 0.0f;
        const float* a2 = &A2h[ld * 12 + c];
        float acc = 0.0f;
        acc = fmaf(ww0, a2[0], acc);
        acc = fmaf(ww1, a2[3], acc);
        acc = fmaf(ww2, a2[6], acc);
        acc = fmaf(ww3, a2[9], acc);
        return acc;
    };

    float g[16];
#pragma unroll
    for (int j = 0; j < 16; j++) g[j] = Gs[j];

    float win[16];
#pragma unroll
    for (int j = 0; j < 16; j++) win[j] = b1(j);

    size_t obase = ((size_t)(c * 2 + b) << 21) + ((size_t)t0 << 14) + (h << 7) + w;
#pragma unroll
    for (int dl = 0; dl < 32; dl++) {
        float acc = 0.0f;
#pragma unroll
        for (int j = 0; j < 16; j++)
            acc = fmaf(g[j], win[(dl + j) & 15], acc);   // j ascending: bit-exact
        d_F2[obase] = acc;
        obase += 16384;
        if (dl < 31) win[dl & 15] = b1(dl + 16);
    }
}

// ---------------- fused convH + convW (convH reads GLOBAL directly; low smem) --------
// grid (8, 128, 2) = (h-tile of 16, d, b); 384 threads
// dyn smem: H [48][129] = 6192 floats; OUT [48][129] = 6192 floats.  total 49536 B
extern __shared__ float dyn_smem[];
__global__ __launch_bounds__(384) void flowHW_kernel() {
    float* H   = dyn_smem;
    float* OUT = dyn_smem + 6192;
    __shared__ float  Gs[16];
    __shared__ double gtmp[16];
    const int t = threadIdx.x;
    const int h0 = blockIdx.x * 16;
    const int d = blockIdx.y, b = blockIdx.z;

    if (t < 16) { double o = (double)(t - 7); gtmp[t] = exp(-o * o / 12.5); }
    __syncthreads();
    if (t < 16) {
        double gs = 0.0;
        for (int j = 0; j < 16; j++) gs += gtmp[j];
        Gs[t] = (float)(gtmp[t] / gs);
    }
    __syncthreads();

    float g[16];
#pragma unroll
    for (int j = 0; j < 16; j++) g[j] = Gs[j];

    // phase 1+2: convH, sliding along h, window filled straight from global F2
    // (32 lanes = consecutive w -> one 128B line per LDG, L2-resident)
    {
        const int c = t >> 7, w = t & 127;
        const float* gcol = d_F2 + ((size_t)(c * 2 + b) << 21) + ((size_t)d << 14) + w;
        float win[16];
#pragma unroll
        for (int j = 0; j < 16; j++) {
            const int hp = h0 - 7 + j;
            win[j] = (hp >= 0 && hp < 128) ? gcol[(size_t)hp << 7] : 0.0f;
        }
#pragma unroll
        for (int hl = 0; hl < 16; hl++) {
            float acc = 0.0f;
#pragma unroll
            for (int j = 0; j < 16; j++)
                acc = fmaf(g[j], win[(hl + j) & 15], acc);
            H[(c * 16 + hl) * 129 + w] = acc;
            if (hl < 15) {
                const int hp = h0 + 9 + hl;   // h0-7+hl+16 >= 9, only upper bound needed
                win[hl & 15] = (hp < 128) ? gcol[(size_t)hp << 7] : 0.0f;
            }
        }
    }
    __syncthreads();

    // phase 3: convW, sliding along w. chunk-major: t = q*48 + pi (pi = c*16+hl)
    {
        const int q = t / 48, pi = t - q * 48;
        const int s0 = q * 16 - 7;
        const float* row = H + pi * 129;
        auto hv = [&](int s) -> float { return (s >= 0 && s < 128) ? row[s] : 0.0f; };
        float win[16];
#pragma unroll
        for (int j = 0; j < 16; j++) win[j] = hv(s0 + j);
        float* orow = OUT + pi * 129 + q * 16;
#pragma unroll
        for (int wl = 0; wl < 16; wl++) {
            float acc = 0.0f;
#pragma unroll
            for (int j = 0; j < 16; j++)
                acc = fmaf(g[j], win[(wl + j) & 15], acc);
            orow[wl] = acc;
            if (wl < 15) win[wl & 15] = hv(s0 + wl + 16);
        }
    }
    __syncthreads();

    // phase 4: coalesced planar store
    {
        const int c = t >> 7, w = t & 127;
        const size_t gbase = ((size_t)(c * 2 + b) << 21) + ((size_t)d << 14) + w;
#pragma unroll
        for (int hl = 0; hl < 16; hl++)
            d_F3[gbase + ((size_t)(h0 + hl) << 7)] = OUT[(c * 16 + hl) * 129 + w];
    }
}

// ---------------- warp: image trilinear + label nearest (R6 gather + __stcs) ---------
__device__ __forceinline__ float4 lerp4(float4 p, float4 q, float t) {
    float4 r;
    r.x = fmaf(t, q.x - p.x, p.x);
    r.y = fmaf(t, q.y - p.y, p.y);
    r.z = fmaf(t, q.z - p.z, p.z);
    r.w = fmaf(t, q.w - p.w, p.w);
    return r;
}

// grid (32, 128, 2) = (h-quad, d, b); 512 threads = 4 h-pencils x 128 w
__global__ __launch_bounds__(512) void warp_kernel(
    const float* __restrict__ img, const int* __restrict__ lab, float* __restrict__ out)
{
    __shared__ float fl[3 * 4 * 128];   // [c][hl][w]
    const int t = threadIdx.x;
    const int d = blockIdx.y, b = blockIdx.z;

    for (int i = t; i < 1536; i += 512) {
        const int c = i >> 9, rem = i & 511, hl2 = rem >> 7, w2 = rem & 127;
        fl[i] = d_F3[((size_t)(c * 2 + b) << 21) + ((size_t)d << 14) + ((blockIdx.x * 4 + hl2) << 7) + w2];
    }
    __syncthreads();

    const int hl = t >> 7, w = t & 127;
    const int h = blockIdx.x * 4 + hl;

    const float f0 = fl[          hl * 128 + w];
    const float f1 = fl[ 512 +    hl * 128 + w];
    const float f2 = fl[1024 +    hl * 128 + w];

    const float wd = __fadd_rn((float)d, __fmul_rn(f0, 35.0f));
    const float wh = __fadd_rn((float)h, __fmul_rn(f1, 35.0f));
    const float ww = __fadd_rn((float)w, __fmul_rn(f2, 35.0f));

    const float fld = floorf(wd), flh = floorf(wh), flw = floorf(ww);
    const float td = wd - fld, th = wh - flh, tw = ww - flw;

    const int id = (int)fld, ih = (int)flh, iw = (int)flw;
    const int d0 = min(max(id,     0), 127), d1 = min(max(id + 1, 0), 127);
    const int h0 = min(max(ih,     0), 127), h1 = min(max(ih + 1, 0), 127);
    const int w0 = min(max(iw,     0), 127), w1 = min(max(iw + 1, 0), 127);

    const float4* __restrict__ I = reinterpret_cast<const float4*>(img);
    const int bbase = b << 21;

    const int r00 = bbase + (d0 * 128 + h0) * 128;
    const int r01 = bbase + (d0 * 128 + h1) * 128;
    const int r10 = bbase + (d1 * 128 + h0) * 128;
    const int r11 = bbase + (d1 * 128 + h1) * 128;

    const float4 a000 = I[r00 + w0], a001 = I[r00 + w1];
    const float4 a010 = I[r01 + w0], a011 = I[r01 + w1];
    const float4 a100 = I[r10 + w0], a101 = I[r10 + w1];
    const float4 a110 = I[r11 + w0], a111 = I[r11 + w1];

    const float4 c00 = lerp4(a000, a001, tw);
    const float4 c01 = lerp4(a010, a011, tw);
    const float4 c10 = lerp4(a100, a101, tw);
    const float4 c11 = lerp4(a110, a111, tw);
    const float4 c0  = lerp4(c00, c01, th);
    const float4 c1  = lerp4(c10, c11, th);

    const int oidx = bbase + (d * 128 + h) * 128 + w;
    __stcs(&reinterpret_cast<float4*>(out)[oidx], lerp4(c0, c1, td));

    const int nd = min(max((int)rintf(wd), 0), 127);
    const int nh = min(max((int)rintf(wh), 0), 127);
    const int nw = min(max((int)rintf(ww), 0), 127);
    __stcs(&out[IMG_ELEMS + oidx], (float)__ldg(&lab[bbase + (nd * 128 + nh) * 128 + nw]));
}

extern "C" void kernel_launch(void* const* d_in, const int* in_sizes, int n_in,
                              void* d_out, int out_size) {
    const float* img    = (const float*)d_in[0];
    const int*   lab    = (const int*)  d_in[1];
    const float* coarse = (const float*)d_in[2];
    float* out = (float*)d_out;

    const int hw_smem = (6192 + 6192) * (int)sizeof(float); // 49536 B
    static int attr_done = 0;
    if (!attr_done) {
        cudaFuncSetAttribute(flowHW_kernel, cudaFuncAttributeMaxDynamicSharedMemorySize, hw_smem);
        attr_done = 1;
    }

    flowD_kernel<<<dim3(4, 128, 2), 384>>>(coarse);
    flowHW_kernel<<<dim3(8, 128, 2), 384, hw_smem>>>();
    warp_kernel<<<dim3(32, 128, 2), 512>>>(img, lab, out);
}